// round 16
// baseline (speedup 1.0000x reference)
#include <cuda_runtime.h>

// LorenzPINN: per-row forward + JVP of a 1->20->20->20->20->3 tanh MLP + Lorenz
// residuals. fp32, transposed f32x2 accumulation, weights in __constant__.
// R11 (third submission; rounds 13-15 were broker infra failures, source never
//      ran): fma-pipe diet — epilogue arithmetic packed as f32x2 (FMUL2/FADD2/
//      FFMA2 on (z0,z1) accumulator pairs, scalar MUFU between, XOR sign-flip
//      for the derivative): -150 fma ops/row on the 85us fma wall. State stays
//      SCALAR (R8 lesson: packed state + reg caps => MOV storm). Occupancy:
//      launch_bounds(64,12) -> 24 warps/SM at natural 80 regs.

#define W  20
#define JP 10
typedef unsigned long long u64;

struct __align__(16) CW {
    u64 w2[W * JP];     // (W2[k][2jj], W2[k][2jj+1]) == raw row-major as u64
    u64 w3[W * JP];
    u64 w4[W * JP];
    u64 wo[3 * W];      // dup'd (w,w), wo[c*W+k] = (Wo[k][c], Wo[k][c])
    u64 b2[JP], b3[JP], b4[JP];   // (b[2jj], b[2jj+1]) == raw as u64
    float w1[W], b1[W], bo[3];
    float c1, c2, c3;
};
__constant__ CW cw;
__device__ CW gstage;

__device__ __forceinline__ u64 pack2(float lo, float hi) {
    u64 r; asm("mov.b64 %0,{%1,%2};" : "=l"(r) : "f"(lo), "f"(hi)); return r;
}
__device__ __forceinline__ u64 dup2(float x) {
    u64 r; asm("mov.b64 %0,{%1,%1};" : "=l"(r) : "f"(x)); return r;
}
__device__ __forceinline__ void unpack2(u64 v, float& lo, float& hi) {
    asm("mov.b64 {%0,%1},%2;" : "=f"(lo), "=f"(hi) : "l"(v));
}
__device__ __forceinline__ u64 ffma2(u64 a, u64 b, u64 c) {
    u64 d; asm("fma.rn.f32x2 %0,%1,%2,%3;" : "=l"(d) : "l"(a), "l"(b), "l"(c)); return d;
}
__device__ __forceinline__ u64 fmul2(u64 a, u64 b) {
    u64 d; asm("mul.rn.f32x2 %0,%1,%2;" : "=l"(d) : "l"(a), "l"(b)); return d;
}
__device__ __forceinline__ u64 fadd2(u64 a, u64 b) {
    u64 d; asm("add.rn.f32x2 %0,%1,%2;" : "=l"(d) : "l"(a), "l"(b)); return d;
}
__device__ __forceinline__ float mufu_ex2(float x) {
    float e; asm("ex2.approx.f32 %0, %1;" : "=f"(e) : "f"(x)); return e;
}
__device__ __forceinline__ float mufu_rcp(float x) {
    float r; asm("rcp.approx.f32 %0, %1;" : "=f"(r) : "f"(x)); return r;
}

#define C2LOG2E 2.885390081777927f       // 2*log2(e)
#define SGNMASK 0x8000000080000000ULL

// scalar tanh (layer 1 only): 1 - 2/(e^{2x}+1)
__device__ __forceinline__ float fast_tanh(float x) {
    return fmaf(-2.0f, mufu_rcp(mufu_ex2(x * C2LOG2E) + 1.0f), 1.0f);
}

// ---- pack kernel: gather weights from d_in buffers into the staging struct ----
__global__ void pack_kernel(const float* __restrict__ W1, const float* __restrict__ b1,
                            const float* __restrict__ W2, const float* __restrict__ b2,
                            const float* __restrict__ W3, const float* __restrict__ b3,
                            const float* __restrict__ W4, const float* __restrict__ b4,
                            const float* __restrict__ Wo, const float* __restrict__ bo,
                            const float* __restrict__ c1, const float* __restrict__ c2,
                            const float* __restrict__ c3) {
    int t = threadIdx.x;
    const u64* pw2 = (const u64*)W2;   // adjacent-j pairs are raw u64s (8B-aligned)
    const u64* pw3 = (const u64*)W3;
    const u64* pw4 = (const u64*)W4;
    for (int i = t; i < W * JP; i += blockDim.x) {
        gstage.w2[i] = pw2[i];
        gstage.w3[i] = pw3[i];
        gstage.w4[i] = pw4[i];
    }
    if (t < 3 * W) {
        int c = t / W, k = t % W;
        float w = Wo[k * 3 + c];
        gstage.wo[c * W + k] = pack2(w, w);
    }
    if (t < JP) {
        gstage.b2[t] = ((const u64*)b2)[t];
        gstage.b3[t] = ((const u64*)b3)[t];
        gstage.b4[t] = ((const u64*)b4)[t];
    }
    if (t < W) {
        gstage.w1[t] = W1[t];
        gstage.b1[t] = b1[t];
    }
    if (t < 3) gstage.bo[t] = bo[t];
    if (t == 0) { gstage.c1 = *c1; gstage.c2 = *c2; gstage.c3 = *c3; }
}

// One hidden layer, transposed, weights from __constant__ (uniform port).
// Epilogue packed: t = 1 - 2*rcp(ex2(Cc*z)+1); td = dp - t^2*dp (XOR sign).
#define LAYERC(SW, SB)                                                        \
    do {                                                                      \
        u64 av[JP], ad[JP];                                                   \
        _Pragma("unroll")                                                     \
        for (int jj = 0; jj < JP; jj++) { av[jj] = cw.SB[jj]; ad[jj] = 0ULL; }\
        _Pragma("unroll")                                                     \
        for (int k = 0; k < W; k++) {                                         \
            u64 hk = dup2(th[k]);                                             \
            u64 dk = dup2(td[k]);                                             \
            _Pragma("unroll")                                                 \
            for (int jj = 0; jj < JP; jj++) {                                 \
                u64 wp = cw.SW[k * JP + jj];                                  \
                av[jj] = ffma2(hk, wp, av[jj]);                               \
                ad[jj] = ffma2(dk, wp, ad[jj]);                               \
            }                                                                 \
        }                                                                     \
        _Pragma("unroll")                                                     \
        for (int jj = 0; jj < JP; jj++) {                                     \
            u64 zc = fmul2(av[jj], Cc);                 /* (c*z0, c*z1) */    \
            float zl, zh; unpack2(zc, zl, zh);                                \
            u64 ep = fadd2(pack2(mufu_ex2(zl), mufu_ex2(zh)), One2);          \
            float el, eh; unpack2(ep, el, eh);                                \
            u64 tt = ffma2(M2, pack2(mufu_rcp(el), mufu_rcp(eh)), One2);      \
            float t0, t1; unpack2(tt, t0, t1);                                \
            th[2 * jj + 0] = t0;                                              \
            th[2 * jj + 1] = t1;                                              \
            u64 s  = fmul2(tt ^ SGNMASK, ad[jj]);       /* -t*dp */           \
            u64 tn = ffma2(tt, s, ad[jj]);              /* dp - t^2*dp */     \
            float d0, d1; unpack2(tn, d0, d1);                                \
            td[2 * jj + 0] = d0;                                              \
            td[2 * jj + 1] = d1;                                              \
        }                                                                     \
    } while (0)

__global__ __launch_bounds__(64, 12)
void lorenz_pinn_kernel(const float* __restrict__ t,
                        float* __restrict__ out, int n) {
    int i = blockIdx.x * blockDim.x + threadIdx.x;
    if (i >= n) return;

    float tv = __ldg(t + i);
    float C1 = cw.c1, C2 = cw.c2, C3 = cw.c3;
    u64 Cc   = dup2(C2LOG2E);
    u64 One2 = dup2(1.0f);
    u64 M2   = dup2(-2.0f);

    // Layer 1: pre = t*W1 + b1, dpre = W1 (tangent of t is 1). Scalar state.
    float th[W], td[W];
#pragma unroll
    for (int j = 0; j < W; j++) {
        float w = cw.w1[j];
        float t0 = fast_tanh(fmaf(tv, w, cw.b1[j]));
        th[j] = t0;
        td[j] = fmaf(-t0, t0 * w, w);
    }

    LAYERC(w2, b2);
    LAYERC(w3, b3);
    LAYERC(w4, b4);

    // Output head: pack (value, tangent) per k; dup'd weights -> acc = (o_c, d_c).
    u64 hd[W];
#pragma unroll
    for (int k = 0; k < W; k++) hd[k] = pack2(th[k], td[k]);

    float o[3], d[3];
#pragma unroll
    for (int c = 0; c < 3; c++) {
        u64 acc = pack2(cw.bo[c], 0.0f);
#pragma unroll
        for (int k = 0; k < W; k++)
            acc = ffma2(hd[k], cw.wo[c * W + k], acc);
        unpack2(acc, o[c], d[c]);
    }

    float x = o[0], y = o[1], z = o[2];
    float fx = d[0] - C1 * (y - x);
    float fy = d[1] - x * (C2 - z) + y;
    float fz = d[2] - x * y + C3 * z;

    float2* po = reinterpret_cast<float2*>(out + (size_t)i * 6);
    po[0] = make_float2(x, y);
    po[1] = make_float2(z, fx);
    po[2] = make_float2(fy, fz);
}

extern "C" void kernel_launch(void* const* d_in, const int* in_sizes, int n_in,
                              void* d_out, int out_size) {
    const float* t  = (const float*)d_in[0];
    const float* W1 = (const float*)d_in[1];
    const float* b1 = (const float*)d_in[2];
    const float* W2 = (const float*)d_in[3];
    const float* b2 = (const float*)d_in[4];
    const float* W3 = (const float*)d_in[5];
    const float* b3 = (const float*)d_in[6];
    const float* W4 = (const float*)d_in[7];
    const float* b4 = (const float*)d_in[8];
    const float* Wo = (const float*)d_in[9];
    const float* bo = (const float*)d_in[10];
    const float* c1 = (const float*)d_in[11];
    const float* c2 = (const float*)d_in[12];
    const float* c3 = (const float*)d_in[13];
    float* out = (float*)d_out;
    int n = in_sizes[0];

    // 1) Gather+pack weights into the device staging struct.
    pack_kernel<<<1, 256>>>(W1, b1, W2, b2, W3, b3, W4, b4, Wo, bo, c1, c2, c3);

    // 2) One D2D copy staging -> __constant__ (graph-capturable memcpy node).
    void* src = nullptr;
    cudaGetSymbolAddress(&src, gstage);
    cudaMemcpyToSymbolAsync(cw, src, sizeof(CW), 0, cudaMemcpyDeviceToDevice, 0);

    // 3) Main kernel.
    int blocks = (n + 63) / 64;
    lorenz_pinn_kernel<<<blocks, 64>>>(t, out, n);
}

// round 17
// speedup vs baseline: 1.1264x; 1.1264x over previous
#include <cuda_runtime.h>

// LorenzPINN: per-row forward + JVP of a 1->20->20->20->20->3 tanh MLP + Lorenz
// residuals. fp32, transposed f32x2 accumulation, weights in __constant__.
// R17: scalar epilogue restored (R11's packed epilogue = +13us alu MOV storm,
//      zero fma savings). New: SCALE FOLDING —
//      (a) value state TH = C*th (C = 2*log2(e)); biases pre-scaled by C so
//          the accumulator IS C*z: kills the FMUL(z*C) per unit.
//      (b) derivative via 1-th^2 = 4r(1-r): td_state = dp*r(1-r), the 4^3
//          deficit after 3 layers folded into asymmetric head weight pairs
//          (Wo/C, 64*Wo). -70 fma ops/row on the 85us fma wall, zero MOVs.
//      launch_bounds(64,12) kept: 24 warps/SM at 80 regs.

#define W  20
#define JP 10
typedef unsigned long long u64;

#define CF   2.885390081777927f      // C = 2*log2(e)
#define M2CF -5.770780163555854f     // -2C

struct __align__(16) CW {
    u64 w2[W * JP];     // raw row-major pairs (W[k][2jj], W[k][2jj+1])
    u64 w3[W * JP];
    u64 w4[W * JP];
    u64 wo[3 * W];      // ASYMMETRIC pairs (Wo/C, 64*Wo) per (c,k)
    u64 b2[JP], b3[JP], b4[JP];   // C-scaled bias pairs (C*b[2jj], C*b[2jj+1])
    float w1c[W], b1c[W];         // C-scaled layer-1 weights/biases
    float w1x4[W];                // 4*W1 for layer-1 derivative
    float bo[3];
    float c1, c2, c3;
};
__constant__ CW cw;
__device__ CW gstage;

__device__ __forceinline__ u64 pack2(float lo, float hi) {
    u64 r; asm("mov.b64 %0,{%1,%2};" : "=l"(r) : "f"(lo), "f"(hi)); return r;
}
__device__ __forceinline__ u64 dup2(float x) {
    u64 r; asm("mov.b64 %0,{%1,%1};" : "=l"(r) : "f"(x)); return r;
}
__device__ __forceinline__ void unpack2(u64 v, float& lo, float& hi) {
    asm("mov.b64 {%0,%1},%2;" : "=f"(lo), "=f"(hi) : "l"(v));
}
__device__ __forceinline__ u64 ffma2(u64 a, u64 b, u64 c) {
    u64 d; asm("fma.rn.f32x2 %0,%1,%2,%3;" : "=l"(d) : "l"(a), "l"(b), "l"(c)); return d;
}
__device__ __forceinline__ float mufu_ex2(float x) {
    float e; asm("ex2.approx.f32 %0, %1;" : "=f"(e) : "f"(x)); return e;
}
__device__ __forceinline__ float mufu_rcp(float x) {
    float r; asm("rcp.approx.f32 %0, %1;" : "=f"(r) : "f"(x)); return r;
}

// ---- pack kernel: gather + pre-scale weights into the staging struct ----
__global__ void pack_kernel(const float* __restrict__ W1, const float* __restrict__ b1,
                            const float* __restrict__ W2, const float* __restrict__ b2,
                            const float* __restrict__ W3, const float* __restrict__ b3,
                            const float* __restrict__ W4, const float* __restrict__ b4,
                            const float* __restrict__ Wo, const float* __restrict__ bo,
                            const float* __restrict__ c1, const float* __restrict__ c2,
                            const float* __restrict__ c3) {
    int t = threadIdx.x;
    const u64* pw2 = (const u64*)W2;   // adjacent-j pairs are raw u64s (8B-aligned)
    const u64* pw3 = (const u64*)W3;
    const u64* pw4 = (const u64*)W4;
    for (int i = t; i < W * JP; i += blockDim.x) {
        gstage.w2[i] = pw2[i];
        gstage.w3[i] = pw3[i];
        gstage.w4[i] = pw4[i];
    }
    if (t < 3 * W) {
        int c = t / W, k = t % W;
        float w = Wo[k * 3 + c];
        gstage.wo[c * W + k] = pack2(w * (1.0f / CF), w * 64.0f);
    }
    if (t < JP) {
        gstage.b2[t] = pack2(CF * b2[2 * t], CF * b2[2 * t + 1]);
        gstage.b3[t] = pack2(CF * b3[2 * t], CF * b3[2 * t + 1]);
        gstage.b4[t] = pack2(CF * b4[2 * t], CF * b4[2 * t + 1]);
    }
    if (t < W) {
        gstage.w1c[t]  = CF * W1[t];
        gstage.b1c[t]  = CF * b1[t];
        gstage.w1x4[t] = 4.0f * W1[t];
    }
    if (t < 3) gstage.bo[t] = bo[t];
    if (t == 0) { gstage.c1 = *c1; gstage.c2 = *c2; gstage.c3 = *c3; }
}

// One hidden layer, transposed, weights from __constant__ (uniform port).
// av accumulates C*z (state is C-scaled); epilogue:
//   r = rcp(ex2(av)+1); TH = C - 2C*r; td_state = dp_state * r*(1-r).
// Tangent state carries a 1/4 factor per layer, absorbed by head weights.
#define LAYERC(SW, SB)                                                        \
    do {                                                                      \
        u64 av[JP], ad[JP];                                                   \
        _Pragma("unroll")                                                     \
        for (int jj = 0; jj < JP; jj++) { av[jj] = cw.SB[jj]; ad[jj] = 0ULL; }\
        _Pragma("unroll")                                                     \
        for (int k = 0; k < W; k++) {                                         \
            u64 hk = dup2(th[k]);                                             \
            u64 dk = dup2(td[k]);                                             \
            _Pragma("unroll")                                                 \
            for (int jj = 0; jj < JP; jj++) {                                 \
                u64 wp = cw.SW[k * JP + jj];                                  \
                av[jj] = ffma2(hk, wp, av[jj]);                               \
                ad[jj] = ffma2(dk, wp, ad[jj]);                               \
            }                                                                 \
        }                                                                     \
        _Pragma("unroll")                                                     \
        for (int jj = 0; jj < JP; jj++) {                                     \
            float z0, z1, dp0, dp1;                                           \
            unpack2(av[jj], z0, z1);           /* already C*z */              \
            unpack2(ad[jj], dp0, dp1);                                        \
            float r0 = mufu_rcp(mufu_ex2(z0) + 1.0f);                         \
            float r1 = mufu_rcp(mufu_ex2(z1) + 1.0f);                         \
            th[2 * jj + 0] = fmaf(M2CF, r0, CF);     /* TH = C*th */          \
            th[2 * jj + 1] = fmaf(M2CF, r1, CF);                              \
            float u0 = fmaf(-r0, r0, r0);            /* r(1-r) */             \
            float u1 = fmaf(-r1, r1, r1);                                     \
            td[2 * jj + 0] = dp0 * u0;               /* td_true/4 per layer */\
            td[2 * jj + 1] = dp1 * u1;                                        \
        }                                                                     \
    } while (0)

__global__ __launch_bounds__(64, 12)
void lorenz_pinn_kernel(const float* __restrict__ t,
                        float* __restrict__ out, int n) {
    int i = blockIdx.x * blockDim.x + threadIdx.x;
    if (i >= n) return;

    float tv = __ldg(t + i);
    float C1 = cw.c1, C2 = cw.c2, C3 = cw.c3;

    // Layer 1: av = C*(t*W1 + b1) via pre-scaled w1c/b1c; TH = C*th;
    // td = (1-th^2)*W1 = 4*W1*r*(1-r) via w1x4 (TRUE scale after layer 1).
    float th[W], td[W];
#pragma unroll
    for (int j = 0; j < W; j++) {
        float zc = fmaf(tv, cw.w1c[j], cw.b1c[j]);
        float r  = mufu_rcp(mufu_ex2(zc) + 1.0f);
        th[j] = fmaf(M2CF, r, CF);
        td[j] = cw.w1x4[j] * fmaf(-r, r, r);
    }

    LAYERC(w2, b2);   // tangent state: td_true/4
    LAYERC(w3, b3);   // td_true/16
    LAYERC(w4, b4);   // td_true/64

    // Output head: hd packs (TH, TD); asymmetric weights (Wo/C, 64*Wo)
    // restore true scales -> acc = (o_c, d_c) exactly.
    u64 hd[W];
#pragma unroll
    for (int k = 0; k < W; k++) hd[k] = pack2(th[k], td[k]);

    float o[3], d[3];
#pragma unroll
    for (int c = 0; c < 3; c++) {
        u64 acc = pack2(cw.bo[c], 0.0f);
#pragma unroll
        for (int k = 0; k < W; k++)
            acc = ffma2(hd[k], cw.wo[c * W + k], acc);
        unpack2(acc, o[c], d[c]);
    }

    float x = o[0], y = o[1], z = o[2];
    float fx = d[0] - C1 * (y - x);
    float fy = d[1] - x * (C2 - z) + y;
    float fz = d[2] - x * y + C3 * z;

    float2* po = reinterpret_cast<float2*>(out + (size_t)i * 6);
    po[0] = make_float2(x, y);
    po[1] = make_float2(z, fx);
    po[2] = make_float2(fy, fz);
}

extern "C" void kernel_launch(void* const* d_in, const int* in_sizes, int n_in,
                              void* d_out, int out_size) {
    const float* t  = (const float*)d_in[0];
    const float* W1 = (const float*)d_in[1];
    const float* b1 = (const float*)d_in[2];
    const float* W2 = (const float*)d_in[3];
    const float* b2 = (const float*)d_in[4];
    const float* W3 = (const float*)d_in[5];
    const float* b3 = (const float*)d_in[6];
    const float* W4 = (const float*)d_in[7];
    const float* b4 = (const float*)d_in[8];
    const float* Wo = (const float*)d_in[9];
    const float* bo = (const float*)d_in[10];
    const float* c1 = (const float*)d_in[11];
    const float* c2 = (const float*)d_in[12];
    const float* c3 = (const float*)d_in[13];
    float* out = (float*)d_out;
    int n = in_sizes[0];

    // 1) Gather + pre-scale weights into the device staging struct.
    pack_kernel<<<1, 256>>>(W1, b1, W2, b2, W3, b3, W4, b4, Wo, bo, c1, c2, c3);

    // 2) One D2D copy staging -> __constant__ (graph-capturable memcpy node).
    void* src = nullptr;
    cudaGetSymbolAddress(&src, gstage);
    cudaMemcpyToSymbolAsync(cw, src, sizeof(CW), 0, cudaMemcpyDeviceToDevice, 0);

    // 3) Main kernel.
    int blocks = (n + 63) / 64;
    lorenz_pinn_kernel<<<blocks, 64>>>(t, out, n);
}